// round 1
// baseline (speedup 1.0000x reference)
#include <cuda_runtime.h>
#include <cuda_bf16.h>
#include <math.h>

// Problem constants
#define BATCH 32768
#define SEQ   8          // N*T = 2*4
#define DIM   256
#define HEADS 8
#define HD    32
#define SCALE 0.17677669529663687f   // 1/sqrt(32)

// Scratch: QKV [B*S, 768] and pooled [B*2, 256]
__device__ float g_qkv[(size_t)BATCH * SEQ * 768];
__device__ float g_pool[(size_t)BATCH * 2 * 256];

// ---------------------------------------------------------------------------
// Tiled fp32 SGEMM:  C[M,N] = A[M,256] @ W(sel-by-column) + bias
// W columns [0,256) -> W0, [256,512) -> W1, [512,768) -> W2 (each [256,256] row-major)
// BM=128, BN=128, BK=16, 256 threads, TM=TN=8
// ---------------------------------------------------------------------------
#define BM 128
#define BN 128
#define BKK 16
#define TM 8
#define TN 8

__global__ __launch_bounds__(256)
void sgemm_kernel(const float* __restrict__ A,
                  const float* __restrict__ W0, const float* __restrict__ W1,
                  const float* __restrict__ W2,
                  const float* __restrict__ b0, const float* __restrict__ b1,
                  const float* __restrict__ b2,
                  float* __restrict__ C, int M, int N)
{
    __shared__ float As[BKK][BM];
    __shared__ float Ws[BKK][BN];

    const int tid = threadIdx.x;
    const int tx = tid & 15;          // N direction
    const int ty = tid >> 4;          // M direction

    const long row0 = (long)blockIdx.y * BM;
    const int  col0 = blockIdx.x * BN;

    // a 128-wide column tile never straddles a 256 boundary
    const int sel = col0 >> 8;
    const float* __restrict__ Wp = (sel == 0) ? W0 : ((sel == 1) ? W1 : W2);
    const float* __restrict__ bp = (sel == 0) ? b0 : ((sel == 1) ? b1 : b2);
    const int wcol0 = col0 & 255;

    float acc[TM][TN];
    #pragma unroll
    for (int i = 0; i < TM; i++)
        #pragma unroll
        for (int j = 0; j < TN; j++) acc[i][j] = 0.f;

    for (int k0 = 0; k0 < 256; k0 += BKK) {
        // Load A tile 128x16 (512 float4, 2 per thread), store transposed
        #pragma unroll
        for (int t = 0; t < 2; t++) {
            int f  = tid + t * 256;          // 0..511
            int r  = f >> 2;                 // row in tile 0..127
            int c4 = (f & 3) * 4;            // col 0,4,8,12
            float4 v = *reinterpret_cast<const float4*>(A + (row0 + r) * 256 + k0 + c4);
            As[c4 + 0][r] = v.x;
            As[c4 + 1][r] = v.y;
            As[c4 + 2][r] = v.z;
            As[c4 + 3][r] = v.w;
        }
        // Load W tile 16x128 (512 float4, 2 per thread)
        #pragma unroll
        for (int t = 0; t < 2; t++) {
            int f  = tid + t * 256;
            int r  = f >> 5;                 // 0..15
            int c4 = (f & 31) * 4;           // 0..124
            float4 v = *reinterpret_cast<const float4*>(Wp + (long)(k0 + r) * 256 + wcol0 + c4);
            *reinterpret_cast<float4*>(&Ws[r][c4]) = v;
        }
        __syncthreads();

        #pragma unroll
        for (int k = 0; k < BKK; k++) {
            float a[TM], b[TN];
            float4 a0 = *reinterpret_cast<const float4*>(&As[k][ty * TM]);
            float4 a1 = *reinterpret_cast<const float4*>(&As[k][ty * TM + 4]);
            a[0]=a0.x; a[1]=a0.y; a[2]=a0.z; a[3]=a0.w;
            a[4]=a1.x; a[5]=a1.y; a[6]=a1.z; a[7]=a1.w;
            float4 bb0 = *reinterpret_cast<const float4*>(&Ws[k][tx * TN]);
            float4 bb1 = *reinterpret_cast<const float4*>(&Ws[k][tx * TN + 4]);
            b[0]=bb0.x; b[1]=bb0.y; b[2]=bb0.z; b[3]=bb0.w;
            b[4]=bb1.x; b[5]=bb1.y; b[6]=bb1.z; b[7]=bb1.w;
            #pragma unroll
            for (int i = 0; i < TM; i++)
                #pragma unroll
                for (int j = 0; j < TN; j++)
                    acc[i][j] = fmaf(a[i], b[j], acc[i][j]);
        }
        __syncthreads();
    }

    // Epilogue: add bias, write out
    #pragma unroll
    for (int i = 0; i < TM; i++) {
        long r = row0 + ty * TM + i;
        #pragma unroll
        for (int j = 0; j < TN; j += 4) {
            int cw = wcol0 + tx * TN + j;    // column within this W (0..255)
            float4 v;
            v.x = acc[i][j + 0] + bp[cw + 0];
            v.y = acc[i][j + 1] + bp[cw + 1];
            v.z = acc[i][j + 2] + bp[cw + 2];
            v.w = acc[i][j + 3] + bp[cw + 3];
            *reinterpret_cast<float4*>(C + r * N + col0 + tx * TN + j) = v;
        }
    }
}

// ---------------------------------------------------------------------------
// Fused: edge modulation + per-head attention + temporal pooling
// 1 CTA (256 threads) per batch; warp h handles head h.
// Reads g_qkv [B*8, 768] (Q|K|V), writes g_pool [B*2, 256].
// ---------------------------------------------------------------------------
__global__ __launch_bounds__(256)
void attn_kernel(const float* __restrict__ e,
                 const float* __restrict__ Wbias,  const float* __restrict__ bbias,
                 const float* __restrict__ Wgate,  const float* __restrict__ bgate,
                 const float* __restrict__ Wscale, const float* __restrict__ bscale,
                 const float* __restrict__ Wshift, const float* __restrict__ bshift,
                 const float* __restrict__ Whs,    const float* __restrict__ bhs)
{
    __shared__ float sQ[HEADS][SEQ][33];
    __shared__ float sK[HEADS][SEQ][33];
    __shared__ float sV[HEADS][SEQ][33];
    __shared__ float sA[HEADS][SEQ][9];

    const int b    = blockIdx.x;
    const int h    = threadIdx.x >> 5;
    const int lane = threadIdx.x & 31;
    const int c    = h * HD + lane;      // full channel 0..255

    const float e0 = e[b * 2 + 0];
    const float e1 = e[b * 2 + 1];

    // Edge-conditioned modulation for channel c
    float gate = 1.f / (1.f + expf(-(e0 * Wgate[c]  + e1 * Wgate[256 + c]  + bgate[c])));
    float scl  = tanhf(        e0 * Wscale[c] + e1 * Wscale[256 + c] + bscale[c]);
    float shf  =               e0 * Wshift[c] + e1 * Wshift[256 + c] + bshift[c];
    float g2 = gate * (1.f + scl);
    float s2 = shf * gate;

    // Per-head scalars
    float eb = e0 * Wbias[h] + e1 * Wbias[8 + h] + bbias[h];
    float hs = tanhf(e0 * Whs[h] + e1 * Whs[8 + h] + bhs[h]);
    const float score_mul = SCALE * (1.f + hs);

    const float* __restrict__ qkv = g_qkv + (long)b * SEQ * 768;
    #pragma unroll
    for (int t = 0; t < SEQ; t++) {
        sQ[h][t][lane] = qkv[t * 768 +       c];
        sK[h][t][lane] = qkv[t * 768 + 256 + c];
        sV[h][t][lane] = qkv[t * 768 + 512 + c] * g2 + s2;   // modulated V
    }
    __syncwarp();

    // 64 scores per head: lane owns pairs (lane) and (lane+32)
    float sc[2];
    #pragma unroll
    for (int p = 0; p < 2; p++) {
        int idx = lane + p * 32;
        int s = idx >> 3, t = idx & 7;
        float acc = 0.f;
        #pragma unroll
        for (int d = 0; d < HD; d++) acc = fmaf(sQ[h][s][d], sK[h][t][d], acc);
        acc *= score_mul;
        if ((s < 4 && t == s + 4) || (s >= 4 && t == s - 4)) acc += eb;
        sc[p] = acc;
    }

    // Row softmax over 8-lane groups (rows of 8 scores)
    #pragma unroll
    for (int p = 0; p < 2; p++) {
        float mx = sc[p];
        #pragma unroll
        for (int o = 4; o >= 1; o >>= 1)
            mx = fmaxf(mx, __shfl_xor_sync(0xffffffffu, mx, o));
        float ex = __expf(sc[p] - mx);
        float sm = ex;
        #pragma unroll
        for (int o = 4; o >= 1; o >>= 1)
            sm += __shfl_xor_sync(0xffffffffu, sm, o);
        sc[p] = ex / sm;
    }
    {
        int s0 = lane >> 3, t0 = lane & 7;
        sA[h][s0][t0]     = sc[0];
        sA[h][s0 + 4][t0] = sc[1];
    }
    __syncwarp();

    // out[s][lane] = sum_t attn[s][t] * V'[t][lane]; then mean-pool over T=4
    float o[SEQ];
    #pragma unroll
    for (int s = 0; s < SEQ; s++) {
        float acc = 0.f;
        #pragma unroll
        for (int t = 0; t < SEQ; t++) acc = fmaf(sA[h][s][t], sV[h][t][lane], acc);
        o[s] = acc;
    }
    float p0 = (o[0] + o[1] + o[2] + o[3]) * 0.25f;
    float p1 = (o[4] + o[5] + o[6] + o[7]) * 0.25f;
    g_pool[((long)b * 2 + 0) * 256 + c] = p0;
    g_pool[((long)b * 2 + 1) * 256 + c] = p1;
}

// ---------------------------------------------------------------------------
extern "C" void kernel_launch(void* const* d_in, const int* in_sizes, int n_in,
                              void* d_out, int out_size)
{
    const float* x      = (const float*)d_in[0];
    const float* e      = (const float*)d_in[1];
    const float* Wq     = (const float*)d_in[2];
    const float* bq     = (const float*)d_in[3];
    const float* Wk     = (const float*)d_in[4];
    const float* bk     = (const float*)d_in[5];
    const float* Wv     = (const float*)d_in[6];
    const float* bv     = (const float*)d_in[7];
    const float* Wo     = (const float*)d_in[8];
    const float* bo     = (const float*)d_in[9];
    const float* Wbias  = (const float*)d_in[10];
    const float* bbias  = (const float*)d_in[11];
    const float* Wgate  = (const float*)d_in[12];
    const float* bgate  = (const float*)d_in[13];
    const float* Wscale = (const float*)d_in[14];
    const float* bscale = (const float*)d_in[15];
    const float* Wshift = (const float*)d_in[16];
    const float* bshift = (const float*)d_in[17];
    const float* Whs    = (const float*)d_in[18];
    const float* bhs    = (const float*)d_in[19];
    float* out = (float*)d_out;

    float* qkv_s = nullptr;
    float* pool_s = nullptr;
    cudaGetSymbolAddress((void**)&qkv_s, g_qkv);
    cudaGetSymbolAddress((void**)&pool_s, g_pool);

    // 1) QKV projection: [262144, 256] @ [256, 768]
    {
        dim3 grid(768 / BN, (BATCH * SEQ) / BM);
        sgemm_kernel<<<grid, 256>>>(x, Wq, Wk, Wv, bq, bk, bv,
                                    qkv_s, BATCH * SEQ, 768);
    }

    // 2) Modulation + attention + pooling
    attn_kernel<<<BATCH, 256>>>(e, Wbias, bbias, Wgate, bgate,
                                Wscale, bscale, Wshift, bshift, Whs, bhs);

    // 3) Output projection: [65536, 256] @ [256, 256]
    {
        dim3 grid(256 / BN, (BATCH * 2) / BM);
        sgemm_kernel<<<grid, 256>>>(pool_s, Wo, Wo, Wo, bo, bo, bo,
                                    out, BATCH * 2, 256);
    }
}

// round 3
// speedup vs baseline: 2.0335x; 2.0335x over previous
#include <cuda_runtime.h>
#include <cuda_bf16.h>
#include <cstdint>
#include <math.h>

// Problem constants
#define BATCH 32768
#define SEQ   8          // N*T = 2*4
#define DIM   256
#define HEADS 8
#define HD    32
#define SCALE 0.17677669529663687f   // 1/sqrt(32)

// Scratch: QKV [B*S, 768] and pooled [B*2, 256]
__device__ float g_qkv[(size_t)BATCH * SEQ * 768];
__device__ float g_pool[(size_t)BATCH * 2 * 256];

// ---------------------------------------------------------------------------
// Tensor-core GEMM with fp32->bf16 hi/lo split (3-term: hh + hl + lh)
// C[M,N] = A[M,256] @ W(sel-by-column) + bias,  fp32 in/out, ~1e-5 accuracy.
// BM=128, BN=128, BK=32, 256 threads (8 warps as 2x4), warp tile 64x32.
// ---------------------------------------------------------------------------
#define BM 128
#define BN 128
#define BK 32

__device__ __forceinline__ void ldsm4(unsigned* r, unsigned a)
{
    asm volatile("ldmatrix.sync.aligned.m8n8.x4.shared.b16 {%0,%1,%2,%3},[%4];"
                 : "=r"(r[0]), "=r"(r[1]), "=r"(r[2]), "=r"(r[3]) : "r"(a));
}

__device__ __forceinline__ void ldsm4t(unsigned* r, unsigned a)
{
    asm volatile("ldmatrix.sync.aligned.m8n8.x4.trans.shared.b16 {%0,%1,%2,%3},[%4];"
                 : "=r"(r[0]), "=r"(r[1]), "=r"(r[2]), "=r"(r[3]) : "r"(a));
}

__device__ __forceinline__ void mma16816(float* d, const unsigned* a, const unsigned* b)
{
    asm volatile(
        "mma.sync.aligned.m16n8k16.row.col.f32.bf16.bf16.f32 "
        "{%0,%1,%2,%3},{%4,%5,%6,%7},{%8,%9},{%0,%1,%2,%3};"
        : "+f"(d[0]), "+f"(d[1]), "+f"(d[2]), "+f"(d[3])
        : "r"(a[0]), "r"(a[1]), "r"(a[2]), "r"(a[3]), "r"(b[0]), "r"(b[1]));
}

__device__ __forceinline__ unsigned smem_u32(const void* p)
{
    return (unsigned)__cvta_generic_to_shared(p);
}

__global__ __launch_bounds__(256)
void gemm_tc_kernel(const float* __restrict__ A,
                    const float* __restrict__ W0, const float* __restrict__ W1,
                    const float* __restrict__ W2,
                    const float* __restrict__ b0, const float* __restrict__ b1,
                    const float* __restrict__ b2,
                    float* __restrict__ C, int N)
{
    __shared__ __align__(16) __nv_bfloat16 AsH[BM][BK + 8];
    __shared__ __align__(16) __nv_bfloat16 AsL[BM][BK + 8];
    __shared__ __align__(16) __nv_bfloat16 BsH[BK][BN + 8];
    __shared__ __align__(16) __nv_bfloat16 BsL[BK][BN + 8];

    const int tid  = threadIdx.x;
    const int lane = tid & 31;
    const int wid  = tid >> 5;

    const long row0 = (long)blockIdx.y * BM;
    const int  col0 = blockIdx.x * BN;

    // 128-wide column tile never straddles a 256 boundary
    const int sel = col0 >> 8;
    const float* __restrict__ Wp = (sel == 0) ? W0 : ((sel == 1) ? W1 : W2);
    const float* __restrict__ bp = (sel == 0) ? b0 : ((sel == 1) ? b1 : b2);
    const int wcol0 = col0 & 255;

    const int wm = (wid >> 2) * 64;   // warp M offset (0 or 64)
    const int wn = (wid & 3) * 32;    // warp N offset (0/32/64/96)

    float acc[4][4][4];
    #pragma unroll
    for (int i = 0; i < 4; i++) {
        #pragma unroll
        for (int j = 0; j < 4; j++) {
            #pragma unroll
            for (int k = 0; k < 4; k++) {
                acc[i][j][k] = 0.f;
            }
        }
    }

    // prefetch registers
    float4 ar[4];
    float4 wr[4];

    #pragma unroll
    for (int i = 0; i < 4; i++) {
        int id = i * 256 + tid;
        int r  = id >> 3;
        int c4 = (id & 7) * 4;
        ar[i] = *reinterpret_cast<const float4*>(A + (row0 + r) * 256 + c4);
    }
    #pragma unroll
    for (int i = 0; i < 4; i++) {
        int id = i * 256 + tid;
        int r  = id >> 5;
        int c4 = (id & 31) * 4;
        wr[i] = *reinterpret_cast<const float4*>(Wp + (long)r * 256 + wcol0 + c4);
    }

    for (int k0 = 0; k0 < 256; k0 += BK) {
        __syncthreads();   // prior mma reads done before smem overwrite
        #pragma unroll
        for (int i = 0; i < 4; i++) {
            int id = i * 256 + tid;
            int r  = id >> 3;
            int c4 = (id & 7) * 4;
            __nv_bfloat16 hx = __float2bfloat16_rn(ar[i].x);
            __nv_bfloat16 hy = __float2bfloat16_rn(ar[i].y);
            __nv_bfloat16 hz = __float2bfloat16_rn(ar[i].z);
            __nv_bfloat16 hw = __float2bfloat16_rn(ar[i].w);
            AsH[r][c4 + 0] = hx;
            AsH[r][c4 + 1] = hy;
            AsH[r][c4 + 2] = hz;
            AsH[r][c4 + 3] = hw;
            AsL[r][c4 + 0] = __float2bfloat16_rn(ar[i].x - __bfloat162float(hx));
            AsL[r][c4 + 1] = __float2bfloat16_rn(ar[i].y - __bfloat162float(hy));
            AsL[r][c4 + 2] = __float2bfloat16_rn(ar[i].z - __bfloat162float(hz));
            AsL[r][c4 + 3] = __float2bfloat16_rn(ar[i].w - __bfloat162float(hw));
        }
        #pragma unroll
        for (int i = 0; i < 4; i++) {
            int id = i * 256 + tid;
            int r  = id >> 5;
            int c4 = (id & 31) * 4;
            __nv_bfloat16 hx = __float2bfloat16_rn(wr[i].x);
            __nv_bfloat16 hy = __float2bfloat16_rn(wr[i].y);
            __nv_bfloat16 hz = __float2bfloat16_rn(wr[i].z);
            __nv_bfloat16 hw = __float2bfloat16_rn(wr[i].w);
            BsH[r][c4 + 0] = hx;
            BsH[r][c4 + 1] = hy;
            BsH[r][c4 + 2] = hz;
            BsH[r][c4 + 3] = hw;
            BsL[r][c4 + 0] = __float2bfloat16_rn(wr[i].x - __bfloat162float(hx));
            BsL[r][c4 + 1] = __float2bfloat16_rn(wr[i].y - __bfloat162float(hy));
            BsL[r][c4 + 2] = __float2bfloat16_rn(wr[i].z - __bfloat162float(hz));
            BsL[r][c4 + 3] = __float2bfloat16_rn(wr[i].w - __bfloat162float(hw));
        }
        __syncthreads();

        if (k0 + BK < 256) {
            #pragma unroll
            for (int i = 0; i < 4; i++) {
                int id = i * 256 + tid;
                int r  = id >> 3;
                int c4 = (id & 7) * 4;
                ar[i] = *reinterpret_cast<const float4*>(A + (row0 + r) * 256 + (k0 + BK) + c4);
            }
            #pragma unroll
            for (int i = 0; i < 4; i++) {
                int id = i * 256 + tid;
                int r  = id >> 5;
                int c4 = (id & 31) * 4;
                wr[i] = *reinterpret_cast<const float4*>(Wp + (long)(k0 + BK + r) * 256 + wcol0 + c4);
            }
        }

        #pragma unroll
        for (int ks = 0; ks < BK; ks += 16) {
            unsigned aH[4][4];
            unsigned aL[4][4];
            unsigned bH[2][4];
            unsigned bL[2][4];

            int arow = lane & 15;
            int acol = ks + (lane >> 4) * 8;
            #pragma unroll
            for (int mt = 0; mt < 4; mt++) {
                ldsm4(aH[mt], smem_u32(&AsH[wm + mt * 16 + arow][acol]));
                ldsm4(aL[mt], smem_u32(&AsL[wm + mt * 16 + arow][acol]));
            }

            int brow = ks + (lane & 15);
            #pragma unroll
            for (int nt2 = 0; nt2 < 2; nt2++) {
                int bcol = wn + nt2 * 16 + (lane >> 4) * 8;
                ldsm4t(bH[nt2], smem_u32(&BsH[brow][bcol]));
                ldsm4t(bL[nt2], smem_u32(&BsL[brow][bcol]));
            }

            #pragma unroll
            for (int mt = 0; mt < 4; mt++) {
                #pragma unroll
                for (int nt = 0; nt < 4; nt++) {
                    mma16816(acc[mt][nt], aH[mt], &bH[nt >> 1][(nt & 1) * 2]);  // hi*hi
                    mma16816(acc[mt][nt], aH[mt], &bL[nt >> 1][(nt & 1) * 2]);  // hi*lo
                    mma16816(acc[mt][nt], aL[mt], &bH[nt >> 1][(nt & 1) * 2]);  // lo*hi
                }
            }
        }
    }

    // Epilogue: add bias, write fp32
    #pragma unroll
    for (int mt = 0; mt < 4; mt++) {
        long gr = row0 + wm + mt * 16 + (lane >> 2);
        #pragma unroll
        for (int nt = 0; nt < 4; nt++) {
            int cloc = wn + nt * 8 + (lane & 3) * 2;
            int cw   = wcol0 + cloc;
            float bz0 = bp[cw];
            float bz1 = bp[cw + 1];
            float2 v0;
            float2 v1;
            v0.x = acc[mt][nt][0] + bz0;
            v0.y = acc[mt][nt][1] + bz1;
            v1.x = acc[mt][nt][2] + bz0;
            v1.y = acc[mt][nt][3] + bz1;
            *reinterpret_cast<float2*>(C + gr * N + col0 + cloc) = v0;
            *reinterpret_cast<float2*>(C + (gr + 8) * N + col0 + cloc) = v1;
        }
    }
}

// ---------------------------------------------------------------------------
// Fused: edge modulation + per-head attention + temporal pooling
// 1 CTA (256 threads) per batch; warp h handles head h.
// ---------------------------------------------------------------------------
__global__ __launch_bounds__(256)
void attn_kernel(const float* __restrict__ e,
                 const float* __restrict__ Wbias,  const float* __restrict__ bbias,
                 const float* __restrict__ Wgate,  const float* __restrict__ bgate,
                 const float* __restrict__ Wscale, const float* __restrict__ bscale,
                 const float* __restrict__ Wshift, const float* __restrict__ bshift,
                 const float* __restrict__ Whs,    const float* __restrict__ bhs)
{
    __shared__ float sQ[HEADS][SEQ][33];
    __shared__ float sK[HEADS][SEQ][33];
    __shared__ float sV[HEADS][SEQ][33];
    __shared__ float sA[HEADS][SEQ][9];

    const int b    = blockIdx.x;
    const int h    = threadIdx.x >> 5;
    const int lane = threadIdx.x & 31;
    const int c    = h * HD + lane;

    const float e0 = e[b * 2 + 0];
    const float e1 = e[b * 2 + 1];

    float gate = 1.f / (1.f + expf(-(e0 * Wgate[c]  + e1 * Wgate[256 + c]  + bgate[c])));
    float scl  = tanhf(        e0 * Wscale[c] + e1 * Wscale[256 + c] + bscale[c]);
    float shf  =               e0 * Wshift[c] + e1 * Wshift[256 + c] + bshift[c];
    float g2 = gate * (1.f + scl);
    float s2 = shf * gate;

    float eb = e0 * Wbias[h] + e1 * Wbias[8 + h] + bbias[h];
    float hs = tanhf(e0 * Whs[h] + e1 * Whs[8 + h] + bhs[h]);
    const float score_mul = SCALE * (1.f + hs);

    const float* __restrict__ qkv = g_qkv + (long)b * SEQ * 768;
    #pragma unroll
    for (int t = 0; t < SEQ; t++) {
        sQ[h][t][lane] = qkv[t * 768 +       c];
        sK[h][t][lane] = qkv[t * 768 + 256 + c];
        sV[h][t][lane] = qkv[t * 768 + 512 + c] * g2 + s2;
    }
    __syncwarp();

    float sc[2];
    #pragma unroll
    for (int p = 0; p < 2; p++) {
        int idx = lane + p * 32;
        int s = idx >> 3;
        int t = idx & 7;
        float acc = 0.f;
        #pragma unroll
        for (int d = 0; d < HD; d++) {
            acc = fmaf(sQ[h][s][d], sK[h][t][d], acc);
        }
        acc *= score_mul;
        if ((s < 4 && t == s + 4) || (s >= 4 && t == s - 4)) {
            acc += eb;
        }
        sc[p] = acc;
    }

    #pragma unroll
    for (int p = 0; p < 2; p++) {
        float mx = sc[p];
        #pragma unroll
        for (int o = 4; o >= 1; o >>= 1) {
            mx = fmaxf(mx, __shfl_xor_sync(0xffffffffu, mx, o));
        }
        float ex = __expf(sc[p] - mx);
        float sm = ex;
        #pragma unroll
        for (int o = 4; o >= 1; o >>= 1) {
            sm += __shfl_xor_sync(0xffffffffu, sm, o);
        }
        sc[p] = ex / sm;
    }

    {
        int s0 = lane >> 3;
        int t0 = lane & 7;
        sA[h][s0][t0]     = sc[0];
        sA[h][s0 + 4][t0] = sc[1];
    }
    __syncwarp();

    float o[SEQ];
    #pragma unroll
    for (int s = 0; s < SEQ; s++) {
        float acc = 0.f;
        #pragma unroll
        for (int t = 0; t < SEQ; t++) {
            acc = fmaf(sA[h][s][t], sV[h][t][lane], acc);
        }
        o[s] = acc;
    }
    float p0 = (o[0] + o[1] + o[2] + o[3]) * 0.25f;
    float p1 = (o[4] + o[5] + o[6] + o[7]) * 0.25f;
    g_pool[((long)b * 2 + 0) * 256 + c] = p0;
    g_pool[((long)b * 2 + 1) * 256 + c] = p1;
}

// ---------------------------------------------------------------------------
extern "C" void kernel_launch(void* const* d_in, const int* in_sizes, int n_in,
                              void* d_out, int out_size)
{
    const float* x      = (const float*)d_in[0];
    const float* e      = (const float*)d_in[1];
    const float* Wq     = (const float*)d_in[2];
    const float* bq     = (const float*)d_in[3];
    const float* Wk     = (const float*)d_in[4];
    const float* bk     = (const float*)d_in[5];
    const float* Wv     = (const float*)d_in[6];
    const float* bv     = (const float*)d_in[7];
    const float* Wo     = (const float*)d_in[8];
    const float* bo     = (const float*)d_in[9];
    const float* Wbias  = (const float*)d_in[10];
    const float* bbias  = (const float*)d_in[11];
    const float* Wgate  = (const float*)d_in[12];
    const float* bgate  = (const float*)d_in[13];
    const float* Wscale = (const float*)d_in[14];
    const float* bscale = (const float*)d_in[15];
    const float* Wshift = (const float*)d_in[16];
    const float* bshift = (const float*)d_in[17];
    const float* Whs    = (const float*)d_in[18];
    const float* bhs    = (const float*)d_in[19];
    float* out = (float*)d_out;

    float* qkv_s = nullptr;
    float* pool_s = nullptr;
    cudaGetSymbolAddress((void**)&qkv_s, g_qkv);
    cudaGetSymbolAddress((void**)&pool_s, g_pool);

    // 1) QKV projection: [262144, 256] @ [256, 768] (tensor cores, bf16 split)
    {
        dim3 grid(768 / BN, (BATCH * SEQ) / BM);
        gemm_tc_kernel<<<grid, 256>>>(x, Wq, Wk, Wv, bq, bk, bv, qkv_s, 768);
    }

    // 2) Modulation + attention + pooling
    attn_kernel<<<BATCH, 256>>>(e, Wbias, bbias, Wgate, bgate,
                                Wscale, bscale, Wshift, bshift, Whs, bhs);

    // 3) Output projection: [65536, 256] @ [256, 256]
    {
        dim3 grid(256 / BN, (BATCH * 2) / BM);
        gemm_tc_kernel<<<grid, 256>>>(pool_s, Wo, Wo, Wo, bo, bo, bo, out, 256);
    }
}

// round 5
// speedup vs baseline: 2.3449x; 1.1532x over previous
#include <cuda_runtime.h>
#include <cuda_bf16.h>
#include <cstdint>
#include <math.h>

// Problem constants
#define BATCH 32768
#define SEQ   8
#define HEADS 8
#define HD    32
#define SCALE 0.17677669529663687f   // 1/sqrt(32)

// Scratch globals
__device__ float          g_qkv[(size_t)BATCH * SEQ * 768];
__device__ __nv_bfloat16  g_a_hi[(size_t)BATCH * SEQ * 256];
__device__ __nv_bfloat16  g_a_lo[(size_t)BATCH * SEQ * 256];
__device__ __nv_bfloat16  g_w_hi[256 * 768];    // QKV weights [k][768]
__device__ __nv_bfloat16  g_w_lo[256 * 768];
__device__ __nv_bfloat16  g_wo_hi[256 * 256];   // Wo [k][256]
__device__ __nv_bfloat16  g_wo_lo[256 * 256];
__device__ __nv_bfloat16  g_pool_hi[(size_t)BATCH * 2 * 256];
__device__ __nv_bfloat16  g_pool_lo[(size_t)BATCH * 2 * 256];

// ---------------------------------------------------------------------------
// PTX helpers (sm_80-class only: ldmatrix / mma.sync / cp.async)
// ---------------------------------------------------------------------------
__device__ __forceinline__ unsigned smem_u32(const void* p)
{
    return (unsigned)__cvta_generic_to_shared(p);
}

__device__ __forceinline__ void ldsm4(unsigned* r, unsigned a)
{
    asm volatile("ldmatrix.sync.aligned.m8n8.x4.shared.b16 {%0,%1,%2,%3},[%4];"
                 : "=r"(r[0]), "=r"(r[1]), "=r"(r[2]), "=r"(r[3]) : "r"(a));
}

__device__ __forceinline__ void ldsm4t(unsigned* r, unsigned a)
{
    asm volatile("ldmatrix.sync.aligned.m8n8.x4.trans.shared.b16 {%0,%1,%2,%3},[%4];"
                 : "=r"(r[0]), "=r"(r[1]), "=r"(r[2]), "=r"(r[3]) : "r"(a));
}

__device__ __forceinline__ void mma16816(float* d, const unsigned* a, const unsigned* b)
{
    asm volatile(
        "mma.sync.aligned.m16n8k16.row.col.f32.bf16.bf16.f32 "
        "{%0,%1,%2,%3},{%4,%5,%6,%7},{%8,%9},{%0,%1,%2,%3};"
        : "+f"(d[0]), "+f"(d[1]), "+f"(d[2]), "+f"(d[3])
        : "r"(a[0]), "r"(a[1]), "r"(a[2]), "r"(a[3]), "r"(b[0]), "r"(b[1]));
}

__device__ __forceinline__ void cpa16(unsigned dst, const void* src)
{
    asm volatile("cp.async.cg.shared.global [%0], [%1], 16;" :: "r"(dst), "l"(src));
}
__device__ __forceinline__ void cpa_commit()
{
    asm volatile("cp.async.commit_group;" ::: "memory");
}
__device__ __forceinline__ void cpa_wait1()
{
    asm volatile("cp.async.wait_group 1;" ::: "memory");
}

// ---------------------------------------------------------------------------
// Pipelined tensor-core GEMM on pre-split bf16 hi/lo operands.
// C[M,Ntot] = A @ W + bias (3-term split: hh + hl + lh), fp32 out.
// A: [M][256] hi/lo.  W: [256][ldw] hi/lo.  BM=128, BN=128, BK=32.
// 8 warps (2x4), warp tile 64x32.  3-stage cp.async pipeline.
// ---------------------------------------------------------------------------
#define BKK 32
#define STAGES 3
#define A_LD 40        // padded row elems (80B rows, 16B aligned)
#define B_LD 136       // padded row elems (272B rows, 16B aligned)
#define A_STAGE_ELN (128 * A_LD)
#define B_STAGE_ELN (32 * B_LD)
#define GEMM_SMEM_BYTES ((2 * STAGES * A_STAGE_ELN + 2 * STAGES * B_STAGE_ELN) * 2)

__global__ __launch_bounds__(256)
void gemm_bf16_kernel(const __nv_bfloat16* __restrict__ Ahi,
                      const __nv_bfloat16* __restrict__ Alo,
                      const __nv_bfloat16* __restrict__ Whi,
                      const __nv_bfloat16* __restrict__ Wlo,
                      const float* __restrict__ b0, const float* __restrict__ b1,
                      const float* __restrict__ b2,
                      float* __restrict__ C, int ldC, int ldw)
{
    extern __shared__ __nv_bfloat16 smem[];
    __nv_bfloat16* const saH = smem;
    __nv_bfloat16* const saL = saH + STAGES * A_STAGE_ELN;
    __nv_bfloat16* const sbH = saL + STAGES * A_STAGE_ELN;
    __nv_bfloat16* const sbL = sbH + STAGES * B_STAGE_ELN;

    const int tid  = threadIdx.x;
    const int lane = tid & 31;
    const int wid  = tid >> 5;

    const long row0 = (long)blockIdx.y * 128;
    const int  col0 = blockIdx.x * 128;
    const int  sel  = col0 >> 8;
    const float* __restrict__ bp = (sel == 0) ? b0 : ((sel == 1) ? b1 : b2);
    const int wcol0 = col0 & 255;

    const int wm = (wid >> 2) * 64;   // warp M offset
    const int wn = (wid & 3) * 32;    // warp N offset

    float acc[4][4][4];
    #pragma unroll
    for (int i = 0; i < 4; i++) {
        #pragma unroll
        for (int j = 0; j < 4; j++) {
            #pragma unroll
            for (int k = 0; k < 4; k++) {
                acc[i][j][k] = 0.f;
            }
        }
    }

    // stage loader: chunk -> buffer chunk%3
    auto load_stage = [&](int chunk) {
        const int st = chunk % STAGES;
        const int k0 = chunk * BKK;
        #pragma unroll
        for (int t = 0; t < 2; t++) {
            const int id = t * 256 + tid;        // 0..511
            const int r  = id >> 2;              // 0..127
            const int c8 = (id & 3) * 8;         // 0,8,16,24
            cpa16(smem_u32(saH + st * A_STAGE_ELN + r * A_LD + c8),
                  Ahi + (row0 + r) * 256 + k0 + c8);
            cpa16(smem_u32(saL + st * A_STAGE_ELN + r * A_LD + c8),
                  Alo + (row0 + r) * 256 + k0 + c8);
        }
        #pragma unroll
        for (int t = 0; t < 2; t++) {
            const int id = t * 256 + tid;        // 0..511
            const int r  = id >> 4;              // 0..31
            const int c8 = (id & 15) * 8;        // 0..120
            cpa16(smem_u32(sbH + st * B_STAGE_ELN + r * B_LD + c8),
                  Whi + (size_t)(k0 + r) * ldw + col0 + c8);
            cpa16(smem_u32(sbL + st * B_STAGE_ELN + r * B_LD + c8),
                  Wlo + (size_t)(k0 + r) * ldw + col0 + c8);
        }
    };

    load_stage(0);
    cpa_commit();
    load_stage(1);
    cpa_commit();

    #pragma unroll 1
    for (int ch = 0; ch < 8; ch++) {
        cpa_wait1();            // chunk ch arrived (only newest group may pend)
        __syncthreads();        // all warps see data; prev compute on reuse-buf done

        if (ch + 2 < 8) {
            load_stage(ch + 2);
        }
        cpa_commit();           // commit every iter (possibly empty) for wait math

        const int st = ch % STAGES;
        const __nv_bfloat16* aHs = saH + st * A_STAGE_ELN;
        const __nv_bfloat16* aLs = saL + st * A_STAGE_ELN;
        const __nv_bfloat16* bHs = sbH + st * B_STAGE_ELN;
        const __nv_bfloat16* bLs = sbL + st * B_STAGE_ELN;

        #pragma unroll
        for (int ks = 0; ks < BKK; ks += 16) {
            unsigned aHf[4][4];
            unsigned aLf[4][4];
            unsigned bHf[2][4];
            unsigned bLf[2][4];

            const int arow = lane & 15;
            const int acol = ks + (lane >> 4) * 8;
            #pragma unroll
            for (int mt = 0; mt < 4; mt++) {
                ldsm4(aHf[mt], smem_u32(aHs + (wm + mt * 16 + arow) * A_LD + acol));
                ldsm4(aLf[mt], smem_u32(aLs + (wm + mt * 16 + arow) * A_LD + acol));
            }
            const int brow = ks + (lane & 15);
            #pragma unroll
            for (int nt2 = 0; nt2 < 2; nt2++) {
                const int bcol = wn + nt2 * 16 + (lane >> 4) * 8;
                ldsm4t(bHf[nt2], smem_u32(bHs + brow * B_LD + bcol));
                ldsm4t(bLf[nt2], smem_u32(bLs + brow * B_LD + bcol));
            }
            #pragma unroll
            for (int mt = 0; mt < 4; mt++) {
                #pragma unroll
                for (int nt = 0; nt < 4; nt++) {
                    mma16816(acc[mt][nt], aHf[mt], &bHf[nt >> 1][(nt & 1) * 2]);  // hi*hi
                    mma16816(acc[mt][nt], aHf[mt], &bLf[nt >> 1][(nt & 1) * 2]);  // hi*lo
                    mma16816(acc[mt][nt], aLf[mt], &bHf[nt >> 1][(nt & 1) * 2]);  // lo*hi
                }
            }
        }
    }

    // Epilogue: add bias, write fp32
    #pragma unroll
    for (int mt = 0; mt < 4; mt++) {
        const long gr = row0 + wm + mt * 16 + (lane >> 2);
        #pragma unroll
        for (int nt = 0; nt < 4; nt++) {
            const int cloc = wn + nt * 8 + (lane & 3) * 2;
            const int cw   = wcol0 + cloc;
            const float bz0 = bp[cw];
            const float bz1 = bp[cw + 1];
            float2 v0;
            float2 v1;
            v0.x = acc[mt][nt][0] + bz0;
            v0.y = acc[mt][nt][1] + bz1;
            v1.x = acc[mt][nt][2] + bz0;
            v1.y = acc[mt][nt][3] + bz1;
            *reinterpret_cast<float2*>(C + gr * ldC + col0 + cloc) = v0;
            *reinterpret_cast<float2*>(C + (gr + 8) * ldC + col0 + cloc) = v1;
        }
    }
}

// ---------------------------------------------------------------------------
// fp32 -> bf16 hi/lo pre-conversion of x (one float4 per thread)
// ---------------------------------------------------------------------------
__global__ __launch_bounds__(256)
void convert_x_kernel(const float* __restrict__ x)
{
    const size_t i = (size_t)blockIdx.x * 256 + threadIdx.x;
    const float4 v = reinterpret_cast<const float4*>(x)[i];
    __nv_bfloat16 hx = __float2bfloat16_rn(v.x);
    __nv_bfloat16 hy = __float2bfloat16_rn(v.y);
    __nv_bfloat16 hz = __float2bfloat16_rn(v.z);
    __nv_bfloat16 hw = __float2bfloat16_rn(v.w);
    __nv_bfloat162 h01; h01.x = hx; h01.y = hy;
    __nv_bfloat162 h23; h23.x = hz; h23.y = hw;
    __nv_bfloat162 l01;
    l01.x = __float2bfloat16_rn(v.x - __bfloat162float(hx));
    l01.y = __float2bfloat16_rn(v.y - __bfloat162float(hy));
    __nv_bfloat162 l23;
    l23.x = __float2bfloat16_rn(v.z - __bfloat162float(hz));
    l23.y = __float2bfloat16_rn(v.w - __bfloat162float(hw));
    reinterpret_cast<__nv_bfloat162*>(g_a_hi)[i * 2 + 0] = h01;
    reinterpret_cast<__nv_bfloat162*>(g_a_hi)[i * 2 + 1] = h23;
    reinterpret_cast<__nv_bfloat162*>(g_a_lo)[i * 2 + 0] = l01;
    reinterpret_cast<__nv_bfloat162*>(g_a_lo)[i * 2 + 1] = l23;
}

// ---------------------------------------------------------------------------
// Weight hi/lo conversion (keeps [k][n] layout):
// g_w[k][768] = {Wq | Wk | Wv},  g_wo[k][256] = Wo
// grid 256 (k rows), 256 threads (n)
// ---------------------------------------------------------------------------
__global__ __launch_bounds__(256)
void convert_w_kernel(const float* __restrict__ Wq, const float* __restrict__ Wk,
                      const float* __restrict__ Wv, const float* __restrict__ Wo)
{
    const int k = blockIdx.x;
    const int n = threadIdx.x;
    {
        const float v = Wq[k * 256 + n];
        __nv_bfloat16 h = __float2bfloat16_rn(v);
        g_w_hi[k * 768 + n] = h;
        g_w_lo[k * 768 + n] = __float2bfloat16_rn(v - __bfloat162float(h));
    }
    {
        const float v = Wk[k * 256 + n];
        __nv_bfloat16 h = __float2bfloat16_rn(v);
        g_w_hi[k * 768 + 256 + n] = h;
        g_w_lo[k * 768 + 256 + n] = __float2bfloat16_rn(v - __bfloat162float(h));
    }
    {
        const float v = Wv[k * 256 + n];
        __nv_bfloat16 h = __float2bfloat16_rn(v);
        g_w_hi[k * 768 + 512 + n] = h;
        g_w_lo[k * 768 + 512 + n] = __float2bfloat16_rn(v - __bfloat162float(h));
    }
    {
        const float v = Wo[k * 256 + n];
        __nv_bfloat16 h = __float2bfloat16_rn(v);
        g_wo_hi[k * 256 + n] = h;
        g_wo_lo[k * 256 + n] = __float2bfloat16_rn(v - __bfloat162float(h));
    }
}

// ---------------------------------------------------------------------------
// Fused: edge modulation + per-head attention + temporal pooling
// 1 CTA (256 threads) per batch; warp h handles head h.
// Writes pooled output directly as bf16 hi/lo for GEMM2.
// ---------------------------------------------------------------------------
__global__ __launch_bounds__(256)
void attn_kernel(const float* __restrict__ e,
                 const float* __restrict__ Wbias,  const float* __restrict__ bbias,
                 const float* __restrict__ Wgate,  const float* __restrict__ bgate,
                 const float* __restrict__ Wscale, const float* __restrict__ bscale,
                 const float* __restrict__ Wshift, const float* __restrict__ bshift,
                 const float* __restrict__ Whs,    const float* __restrict__ bhs)
{
    __shared__ float sQ[HEADS][SEQ][33];
    __shared__ float sK[HEADS][SEQ][33];
    __shared__ float sV[HEADS][SEQ][33];
    __shared__ float sA[HEADS][SEQ][9];

    const int b    = blockIdx.x;
    const int h    = threadIdx.x >> 5;
    const int lane = threadIdx.x & 31;
    const int c    = h * HD + lane;

    const float e0 = e[b * 2 + 0];
    const float e1 = e[b * 2 + 1];

    float gate = 1.f / (1.f + expf(-(e0 * Wgate[c]  + e1 * Wgate[256 + c]  + bgate[c])));
    float scl  = tanhf(        e0 * Wscale[c] + e1 * Wscale[256 + c] + bscale[c]);
    float shf  =               e0 * Wshift[c] + e1 * Wshift[256 + c] + bshift[c];
    float g2 = gate * (1.f + scl);
    float s2 = shf * gate;

    float eb = e0 * Wbias[h] + e1 * Wbias[8 + h] + bbias[h];
    float hs = tanhf(e0 * Whs[h] + e1 * Whs[8 + h] + bhs[h]);
    const float score_mul = SCALE * (1.f + hs);

    const float* __restrict__ qkv = g_qkv + (long)b * SEQ * 768;
    #pragma unroll
    for (int t = 0; t < SEQ; t++) {
        sQ[h][t][lane] = qkv[t * 768 +       c];
        sK[h][t][lane] = qkv[t * 768 + 256 + c];
        sV[h][t][lane] = qkv[t * 768 + 512 + c] * g2 + s2;
    }
    __syncwarp();

    float sc[2];
    #pragma unroll
    for (int p = 0; p < 2; p++) {
        int idx = lane + p * 32;
        int s = idx >> 3;
        int t = idx & 7;
        float acc = 0.f;
        #pragma unroll
        for (int d = 0; d < HD; d++) {
            acc = fmaf(sQ[h][s][d], sK[h][t][d], acc);
        }
        acc *= score_mul;
        if ((s < 4 && t == s + 4) || (s >= 4 && t == s - 4)) {
            acc += eb;
        }
        sc[p] = acc;
    }

    #pragma unroll
    for (int p = 0; p < 2; p++) {
        float mx = sc[p];
        #pragma unroll
        for (int o = 4; o >= 1; o >>= 1) {
            mx = fmaxf(mx, __shfl_xor_sync(0xffffffffu, mx, o));
        }
        float ex = __expf(sc[p] - mx);
        float sm = ex;
        #pragma unroll
        for (int o = 4; o >= 1; o >>= 1) {
            sm += __shfl_xor_sync(0xffffffffu, sm, o);
        }
        sc[p] = ex / sm;
    }

    {
        int s0 = lane >> 3;
        int t0 = lane & 7;
        sA[h][s0][t0]     = sc[0];
        sA[h][s0 + 4][t0] = sc[1];
    }
    __syncwarp();

    float o[SEQ];
    #pragma unroll
    for (int s = 0; s < SEQ; s++) {
        float acc = 0.f;
        #pragma unroll
        for (int t = 0; t < SEQ; t++) {
            acc = fmaf(sA[h][s][t], sV[h][t][lane], acc);
        }
        o[s] = acc;
    }
    float p0 = (o[0] + o[1] + o[2] + o[3]) * 0.25f;
    float p1 = (o[4] + o[5] + o[6] + o[7]) * 0.25f;

    const long i0 = ((long)b * 2 + 0) * 256 + c;
    const long i1 = ((long)b * 2 + 1) * 256 + c;
    __nv_bfloat16 h0 = __float2bfloat16_rn(p0);
    __nv_bfloat16 h1 = __float2bfloat16_rn(p1);
    g_pool_hi[i0] = h0;
    g_pool_lo[i0] = __float2bfloat16_rn(p0 - __bfloat162float(h0));
    g_pool_hi[i1] = h1;
    g_pool_lo[i1] = __float2bfloat16_rn(p1 - __bfloat162float(h1));
}

// ---------------------------------------------------------------------------
extern "C" void kernel_launch(void* const* d_in, const int* in_sizes, int n_in,
                              void* d_out, int out_size)
{
    const float* x      = (const float*)d_in[0];
    const float* e      = (const float*)d_in[1];
    const float* Wq     = (const float*)d_in[2];
    const float* bq     = (const float*)d_in[3];
    const float* Wk     = (const float*)d_in[4];
    const float* bk     = (const float*)d_in[5];
    const float* Wv     = (const float*)d_in[6];
    const float* bv     = (const float*)d_in[7];
    const float* Wo     = (const float*)d_in[8];
    const float* bo     = (const float*)d_in[9];
    const float* Wbias  = (const float*)d_in[10];
    const float* bbias  = (const float*)d_in[11];
    const float* Wgate  = (const float*)d_in[12];
    const float* bgate  = (const float*)d_in[13];
    const float* Wscale = (const float*)d_in[14];
    const float* bscale = (const float*)d_in[15];
    const float* Wshift = (const float*)d_in[16];
    const float* bshift = (const float*)d_in[17];
    const float* Whs    = (const float*)d_in[18];
    const float* bhs    = (const float*)d_in[19];
    float* out = (float*)d_out;

    float* qkv_p = nullptr;
    __nv_bfloat16 *ahi_p = nullptr, *alo_p = nullptr;
    __nv_bfloat16 *whi_p = nullptr, *wlo_p = nullptr;
    __nv_bfloat16 *wohi_p = nullptr, *wolo_p = nullptr;
    __nv_bfloat16 *phi_p = nullptr, *plo_p = nullptr;
    cudaGetSymbolAddress((void**)&qkv_p,  g_qkv);
    cudaGetSymbolAddress((void**)&ahi_p,  g_a_hi);
    cudaGetSymbolAddress((void**)&alo_p,  g_a_lo);
    cudaGetSymbolAddress((void**)&whi_p,  g_w_hi);
    cudaGetSymbolAddress((void**)&wlo_p,  g_w_lo);
    cudaGetSymbolAddress((void**)&wohi_p, g_wo_hi);
    cudaGetSymbolAddress((void**)&wolo_p, g_wo_lo);
    cudaGetSymbolAddress((void**)&phi_p,  g_pool_hi);
    cudaGetSymbolAddress((void**)&plo_p,  g_pool_lo);

    cudaFuncSetAttribute(gemm_bf16_kernel,
                         cudaFuncAttributeMaxDynamicSharedMemorySize, GEMM_SMEM_BYTES);

    // 0) pre-convert inputs and weights to bf16 hi/lo
    convert_x_kernel<<<65536, 256>>>(x);
    convert_w_kernel<<<256, 256>>>(Wq, Wk, Wv, Wo);

    // 1) QKV projection: [262144,256] @ [256,768]
    {
        dim3 grid(6, 2048);
        gemm_bf16_kernel<<<grid, 256, GEMM_SMEM_BYTES>>>(
            ahi_p, alo_p, whi_p, wlo_p, bq, bk, bv, qkv_p, 768, 768);
    }

    // 2) Modulation + attention + pooling (emits pool hi/lo bf16)
    attn_kernel<<<BATCH, 256>>>(e, Wbias, bbias, Wgate, bgate,
                                Wscale, bscale, Wshift, bshift, Whs, bhs);

    // 3) Output projection: [65536,256] @ [256,256]
    {
        dim3 grid(2, 512);
        gemm_bf16_kernel<<<grid, 256, GEMM_SMEM_BYTES>>>(
            phi_p, plo_p, wohi_p, wolo_p, bo, bo, bo, out, 256, 256);
    }
}